// round 16
// baseline (speedup 1.0000x reference)
#include <cuda_runtime.h>
#include <cuda_fp16.h>
#include <cuda_bf16.h>
#include <cstdint>
#include <limits.h>

#define NMAX 100000
#define NPAD 100096   // 782 * 128: gemm2/3 A-tile cp.async never reads past g_Gh
#define EMAX 1600000
#define EPAD (EMAX + 8 * NMAX)   // padded CSR capacity
#define NGR  64
#define FDIM 128
#define FLAGBIT 0x80000000u

// ---------------- device scratch ----------------
static __device__ __half         g_Th[(size_t)NPAD * FDIM];
static __device__ __nv_bfloat16  g_Gh[(size_t)NPAD * FDIM];
static __device__ float          g_G[(size_t)NMAX * 64];
static __device__ int    g_cntflags[NMAX + 128];   // [0..n)=cnt, [NMAX..]=scan flags (memset 0)
static __device__ int    g_rowptr[NMAX + 1];       // padded offsets (multiples of 8)
static __device__ int    g_cursor[NMAX];
static __device__ int2   g_edge[EPAD];             // {src, weight-bits}; pad slots = {0,0}
static __device__ float  g_dinv[NMAX];
static __device__ float  g_selfw[NMAX];
static __device__ int    g_gstart[NGR];
static __device__ int    g_gend[NGR];
static __device__ int    g_src32[EMAX];
static __device__ int    g_dst32[EMAX];

// ---------------- helpers ----------------
__device__ __forceinline__ void mma_bf16(float* c, const uint32_t* a, const uint32_t* b) {
    asm volatile("mma.sync.aligned.m16n8k16.row.col.f32.bf16.bf16.f32 "
        "{%0,%1,%2,%3}, {%4,%5,%6,%7}, {%8,%9}, {%0,%1,%2,%3};"
        : "+f"(c[0]), "+f"(c[1]), "+f"(c[2]), "+f"(c[3])
        : "r"(a[0]), "r"(a[1]), "r"(a[2]), "r"(a[3]), "r"(b[0]), "r"(b[1]));
}
__device__ __forceinline__ void ldsm_x4(uint32_t* r, uint32_t addr) {
    asm volatile("ldmatrix.sync.aligned.m8n8.x4.shared.b16 {%0,%1,%2,%3}, [%4];"
        : "=r"(r[0]), "=r"(r[1]), "=r"(r[2]), "=r"(r[3]) : "r"(addr));
}
__device__ __forceinline__ void ldsm_x2t(uint32_t* r, uint32_t addr) {
    asm volatile("ldmatrix.sync.aligned.m8n8.x2.trans.shared.b16 {%0,%1}, [%2];"
        : "=r"(r[0]), "=r"(r[1]) : "r"(addr));
}
__device__ __forceinline__ void cp_async16(uint32_t dst, const void* src) {
    asm volatile("cp.async.ca.shared.global [%0], [%1], 16;" :: "r"(dst), "l"(src));
}
__device__ __forceinline__ void split_store(__nv_bfloat16* ph, __nv_bfloat16* pl, float4 v) {
    __nv_bfloat162 h0 = __float22bfloat162_rn(make_float2(v.x, v.y));
    __nv_bfloat162 h1 = __float22bfloat162_rn(make_float2(v.z, v.w));
    float2 r0 = make_float2(v.x - __low2float(h0), v.y - __high2float(h0));
    float2 r1 = make_float2(v.z - __low2float(h1), v.w - __high2float(h1));
    *(__nv_bfloat162*)ph       = h0;
    *(__nv_bfloat162*)(ph + 2) = h1;
    *(__nv_bfloat162*)pl       = __float22bfloat162_rn(r0);
    *(__nv_bfloat162*)(pl + 2) = __float22bfloat162_rn(r1);
}

// ---------------- K1: fused gemm1 + preprocessing ----------------
__global__ __launch_bounds__(256) void k_layer1(
    const float* __restrict__ A, const float* __restrict__ W,
    const void* __restrict__ ei, const void* __restrict__ batch,
    __half* __restrict__ C, int M, int e) {
    constexpr int BN = 128, NJ = 8, WS = 136;
    extern __shared__ __nv_bfloat16 smem[];
    __nv_bfloat16* sWh = smem;
    __nv_bfloat16* sWl = smem + 128 * WS;
    __nv_bfloat16* sA  = smem + 2 * 128 * WS;
    __shared__ int s_is64;

    int tid = threadIdx.x;
    if (tid == 0) {
        const long long* p = (const long long*)ei;
        int ok = 1;
        int m = e < 8 ? e : 8;
        for (int k = 0; k < m; k++) {
            long long v = p[k];
            if (v < 0 || v >= (long long)M) ok = 0;
        }
        s_is64 = ok;
    }
    __syncthreads();
    int is64 = s_is64;
    int m0 = blockIdx.x * 128;

#pragma unroll
    for (int it = 0; it < 16; it++) {
        int idx = tid + it * 256;
        int r = idx >> 5, q = idx & 31;
        float4 v = ((const float4*)W)[idx];
        split_store(&sWh[r * WS + q * 4], &sWl[r * WS + q * 4], v);
    }
#pragma unroll
    for (int it = 0; it < 16; it++) {
        int idx = tid + it * 256;
        int r = idx >> 5, q = idx & 31;
        int row = m0 + r;
        float4 v = make_float4(0.f, 0.f, 0.f, 0.f);
        if (row < M) v = ((const float4*)A)[(size_t)row * 32 + q];
        __nv_bfloat162 h0 = __float22bfloat162_rn(make_float2(v.x, v.y));
        __nv_bfloat162 h1 = __float22bfloat162_rn(make_float2(v.z, v.w));
        *(__nv_bfloat162*)&sA[r * WS + q * 4]     = h0;
        *(__nv_bfloat162*)&sA[r * WS + q * 4 + 2] = h1;
    }

    int nt = gridDim.x * 256;
    for (int i = blockIdx.x * 256 + tid; i < e; i += nt) {
        int s, d;
        if (is64) {
            const long long* p = (const long long*)ei;
            s = (int)p[i]; d = (int)p[(size_t)e + i];
        } else {
            const int* p = (const int*)ei;
            s = p[i]; d = p[(size_t)e + i];
        }
        g_src32[i] = s;
        g_dst32[i] = d;
        atomicAdd(&g_cntflags[d], 1);
    }
    for (int i = blockIdx.x * 256 + tid; i < M; i += nt) {
        int b, bp;
        if (is64) {
            const long long* p = (const long long*)batch;
            b = (int)p[i];
            bp = (i > 0) ? (int)p[i - 1] : -1;
        } else {
            const int* p = (const int*)batch;
            b = p[i];
            bp = (i > 0) ? p[i - 1] : -1;
        }
        if (i == 0) {
            g_gstart[b] = 0;
            for (int q = 0; q < b; q++) { g_gstart[q] = 0; g_gend[q] = 0; }
        } else if (bp != b) {
            g_gend[bp] = i;
            g_gstart[b] = i;
            for (int q = bp + 1; q < b; q++) { g_gstart[q] = i; g_gend[q] = i; }
        }
        if (i == M - 1) {
            g_gend[b] = M;
            for (int q = b + 1; q < NGR; q++) { g_gstart[q] = M; g_gend[q] = M; }
        }
    }
    __syncthreads();

    int w = tid >> 5, lane = tid & 31;
    int grp = lane >> 2, tig = lane & 3;
    int wm = (w & 3) * 32;
    int wn = (w >> 2) * (NJ * 8);
    int l15 = lane & 15;

    float c[2][NJ][4];
#pragma unroll
    for (int i = 0; i < 2; i++)
#pragma unroll
        for (int j = 0; j < NJ; j++)
#pragma unroll
            for (int q = 0; q < 4; q++) c[i][j][q] = 0.f;

#pragma unroll
    for (int k16 = 0; k16 < 128; k16 += 16) {
        uint32_t a[2][4];
#pragma unroll
        for (int i = 0; i < 2; i++) {
            uint32_t addr = (uint32_t)__cvta_generic_to_shared(
                &sA[(wm + i * 16 + l15) * WS + k16 + (lane >> 4) * 8]);
            ldsm_x4(a[i], addr);
        }
        uint32_t b[NJ][2];
#pragma unroll
        for (int j = 0; j < NJ; j++) {
            uint32_t addr = (uint32_t)__cvta_generic_to_shared(
                &sWh[(k16 + l15) * WS + wn + j * 8]);
            ldsm_x2t(b[j], addr);
        }
#pragma unroll
        for (int i = 0; i < 2; i++)
#pragma unroll
            for (int j = 0; j < NJ; j++) mma_bf16(c[i][j], a[i], b[j]);
#pragma unroll
        for (int j = 0; j < NJ; j++) {
            uint32_t addr = (uint32_t)__cvta_generic_to_shared(
                &sWl[(k16 + l15) * WS + wn + j * 8]);
            ldsm_x2t(b[j], addr);
        }
#pragma unroll
        for (int i = 0; i < 2; i++)
#pragma unroll
            for (int j = 0; j < NJ; j++) mma_bf16(c[i][j], a[i], b[j]);
    }

#pragma unroll
    for (int i = 0; i < 2; i++) {
        int r0 = m0 + wm + i * 16 + grp;
        int r1 = r0 + 8;
#pragma unroll
        for (int j = 0; j < NJ; j++) {
            int col = wn + j * 8 + tig * 2;
            if (r0 < M) *(__half2*)&C[(size_t)r0 * BN + col] = __floats2half2_rn(c[i][j][0], c[i][j][1]);
            if (r1 < M) *(__half2*)&C[(size_t)r1 * BN + col] = __floats2half2_rn(c[i][j][2], c[i][j][3]);
        }
    }
}

// ---------------- K2: lookback scan over padded counts (+ dinv/selfw/cursor + pad writes) ----
__global__ void k_prefix(int n) {
    __shared__ int sh[256];
    __shared__ int s_base;
    int b = blockIdx.x, t = threadIdx.x;
    int idx0 = b * 1024 + t * 4;
    int c[4]; int tot = 0;
#pragma unroll
    for (int j = 0; j < 4; j++) {
        int id = idx0 + j;
        c[j] = (id < n) ? g_cntflags[id] : 0;
        tot += (c[j] + 7) & ~7;
    }
    sh[t] = tot;
    __syncthreads();
    for (int d = 1; d < 256; d <<= 1) {
        int v = (t >= d) ? sh[t - d] : 0;
        __syncthreads();
        sh[t] += v;
        __syncthreads();
    }
    int incl = sh[t];
    int agg  = sh[255];
    if (t == 0) atomicExch(&g_cntflags[NMAX + b], (int)((unsigned)agg | FLAGBIT));
    int partial = 0;
    for (int j = t; j < b; j += 256) {
        int v;
        do { v = *(volatile int*)&g_cntflags[NMAX + j]; } while (!((unsigned)v & FLAGBIT));
        partial += (int)((unsigned)v & ~FLAGBIT);
    }
    __syncthreads();
    sh[t] = partial;
    __syncthreads();
    for (int d = 128; d > 0; d >>= 1) {
        if (t < d) sh[t] += sh[t + d];
        __syncthreads();
    }
    if (t == 0) s_base = sh[0];
    __syncthreads();
    int run = s_base + incl - tot;
#pragma unroll
    for (int j = 0; j < 4; j++) {
        int id = idx0 + j;
        if (id < n) {
            int pc = (c[j] + 7) & ~7;
            g_rowptr[id] = run;
            g_cursor[id] = run;
            float di = rsqrtf((float)(c[j] + 1));
            g_dinv[id] = di;
            g_selfw[id] = di * di;
            for (int q = c[j]; q < pc; q++) g_edge[run + q] = make_int2(0, 0);
            run += pc;
            if (id == n - 1) g_rowptr[n] = run;
        }
    }
}

// ---------------- K3: CSR build ----------------
__global__ void k_csr(int e) {
    int i = blockIdx.x * blockDim.x + threadIdx.x;
    if (i >= e) return;
    int s = g_src32[i], d = g_dst32[i];
    float w = g_dinv[s] * g_dinv[d];
    int pos = atomicAdd(&g_cursor[d], 1);
    g_edge[pos] = make_int2(s, __float_as_int(w));
}

// ---------------- gemm2/3 ----------------
template <int BN>
__global__ __launch_bounds__(256) void k_gemm_bf(const __nv_bfloat16* __restrict__ A,
                                                 const float* __restrict__ W,
                                                 __half* __restrict__ C, int M) {
    constexpr int NJ = BN / 16;
    constexpr int WS = BN + 8;
    extern __shared__ __nv_bfloat16 smem[];
    __nv_bfloat16* sWh = smem;
    __nv_bfloat16* sWl = smem + 128 * WS;
    __nv_bfloat16* sA  = smem + 2 * 128 * WS;

    int tid = threadIdx.x;
    int w = tid >> 5, lane = tid & 31;
    int grp = lane >> 2, tig = lane & 3;
    int wm = (w & 3) * 32;
    int wn = (w >> 2) * (NJ * 8);
    int m0 = blockIdx.x * 128;
    int l15 = lane & 15;

#pragma unroll
    for (int t = 0; t < 4; t++) {
#pragma unroll
        for (int cch = 0; cch < 2; cch++) {
            int idx = tid + cch * 256;
            int row = idx >> 2, q = idx & 3;
            cp_async16((uint32_t)__cvta_generic_to_shared(&sA[(t * 128 + row) * 40 + q * 8]),
                       &A[(size_t)(m0 + row) * 128 + t * 32 + q * 8]);
        }
        asm volatile("cp.async.commit_group;");
    }
#pragma unroll
    for (int it = tid; it < 128 * BN / 4; it += 256) {
        int r = it / (BN / 4), q = it % (BN / 4);
        float4 v = ((const float4*)W)[it];
        split_store(&sWh[r * WS + q * 4], &sWl[r * WS + q * 4], v);
    }

    float c[2][NJ][4];
#pragma unroll
    for (int i = 0; i < 2; i++)
#pragma unroll
        for (int j = 0; j < NJ; j++)
#pragma unroll
            for (int q = 0; q < 4; q++) c[i][j][q] = 0.f;

#pragma unroll
    for (int t = 0; t < 4; t++) {
        if (t == 0)      asm volatile("cp.async.wait_group 3;");
        else if (t == 1) asm volatile("cp.async.wait_group 2;");
        else if (t == 2) asm volatile("cp.async.wait_group 1;");
        else             asm volatile("cp.async.wait_group 0;");
        __syncthreads();
#pragma unroll
        for (int k16 = 0; k16 < 32; k16 += 16) {
            int krow = t * 32 + k16;
            uint32_t a[2][4];
#pragma unroll
            for (int i = 0; i < 2; i++) {
                uint32_t addr = (uint32_t)__cvta_generic_to_shared(
                    &sA[(t * 128 + wm + i * 16 + l15) * 40 + k16 + (lane >> 4) * 8]);
                ldsm_x4(a[i], addr);
            }
            uint32_t b[NJ][2];
#pragma unroll
            for (int j = 0; j < NJ; j++) {
                uint32_t addr = (uint32_t)__cvta_generic_to_shared(
                    &sWh[(krow + l15) * WS + wn + j * 8]);
                ldsm_x2t(b[j], addr);
            }
#pragma unroll
            for (int i = 0; i < 2; i++)
#pragma unroll
                for (int j = 0; j < NJ; j++) mma_bf16(c[i][j], a[i], b[j]);
#pragma unroll
            for (int j = 0; j < NJ; j++) {
                uint32_t addr = (uint32_t)__cvta_generic_to_shared(
                    &sWl[(krow + l15) * WS + wn + j * 8]);
                ldsm_x2t(b[j], addr);
            }
#pragma unroll
            for (int i = 0; i < 2; i++)
#pragma unroll
                for (int j = 0; j < NJ; j++) mma_bf16(c[i][j], a[i], b[j]);
        }
    }

#pragma unroll
    for (int i = 0; i < 2; i++) {
        int r0 = m0 + wm + i * 16 + grp;
        int r1 = r0 + 8;
#pragma unroll
        for (int j = 0; j < NJ; j++) {
            int col = wn + j * 8 + tig * 2;
            if (r0 < M) *(__half2*)&C[(size_t)r0 * BN + col] = __floats2half2_rn(c[i][j][0], c[i][j][1]);
            if (r1 < M) *(__half2*)&C[(size_t)r1 * BN + col] = __floats2half2_rn(c[i][j][2], c[i][j][3]);
        }
    }
}

// ---------------- aggregation: padded CSR, uniform int4 edge loads ----------------
__device__ __forceinline__ float4 h4_to_f4(uint2 v, float4 acc, float w) {
    float2 a = __half22float2(*(__half2*)&v.x);
    float2 b = __half22float2(*(__half2*)&v.y);
    acc.x += w * a.x; acc.y += w * a.y; acc.z += w * b.x; acc.w += w * b.y;
    return acc;
}

__global__ __launch_bounds__(256) void k_agg128(const __half* __restrict__ H,
                                                const float* __restrict__ bias,
                                                __nv_bfloat16* __restrict__ out, int n) {
    int warp = (blockIdx.x * blockDim.x + threadIdx.x) >> 5;
    if (warp >= n) return;
    int lane = threadIdx.x & 31;
    const uint2* H2 = (const uint2*)H;
    float sw = g_selfw[warp];
    float4 acc = h4_to_f4(H2[(size_t)warp * 32 + lane], make_float4(0, 0, 0, 0), sw);
    int beg = g_rowptr[warp], end = g_rowptr[warp + 1];
    for (int j = beg; j < end; j += 8) {
        int4 e0 = *(const int4*)&g_edge[j];
        int4 e1 = *(const int4*)&g_edge[j + 2];
        int4 e2 = *(const int4*)&g_edge[j + 4];
        int4 e3 = *(const int4*)&g_edge[j + 6];
        uint2 g0 = H2[(size_t)e0.x * 32 + lane];
        uint2 g1 = H2[(size_t)e0.z * 32 + lane];
        uint2 g2 = H2[(size_t)e1.x * 32 + lane];
        uint2 g3 = H2[(size_t)e1.z * 32 + lane];
        uint2 g4 = H2[(size_t)e2.x * 32 + lane];
        uint2 g5 = H2[(size_t)e2.z * 32 + lane];
        uint2 g6 = H2[(size_t)e3.x * 32 + lane];
        uint2 g7 = H2[(size_t)e3.z * 32 + lane];
        acc = h4_to_f4(g0, acc, __int_as_float(e0.y));
        acc = h4_to_f4(g1, acc, __int_as_float(e0.w));
        acc = h4_to_f4(g2, acc, __int_as_float(e1.y));
        acc = h4_to_f4(g3, acc, __int_as_float(e1.w));
        acc = h4_to_f4(g4, acc, __int_as_float(e2.y));
        acc = h4_to_f4(g5, acc, __int_as_float(e2.w));
        acc = h4_to_f4(g6, acc, __int_as_float(e3.y));
        acc = h4_to_f4(g7, acc, __int_as_float(e3.w));
    }
    float4 b4 = ((const float4*)bias)[lane];
    acc.x = fmaxf(acc.x + b4.x, 0.f);
    acc.y = fmaxf(acc.y + b4.y, 0.f);
    acc.z = fmaxf(acc.z + b4.z, 0.f);
    acc.w = fmaxf(acc.w + b4.w, 0.f);
    __nv_bfloat162 o0 = __float22bfloat162_rn(make_float2(acc.x, acc.y));
    __nv_bfloat162 o1 = __float22bfloat162_rn(make_float2(acc.z, acc.w));
    uint2 o; o.x = *(uint32_t*)&o0; o.y = *(uint32_t*)&o1;
    ((uint2*)out)[(size_t)warp * 32 + lane] = o;
}

__global__ __launch_bounds__(256) void k_agg64(const __half* __restrict__ H,
                                               const float* __restrict__ bias,
                                               float* __restrict__ out, int n) {
    int warp = (blockIdx.x * blockDim.x + threadIdx.x) >> 5;
    if (warp >= n) return;
    int lane = threadIdx.x & 31;
    const uint32_t* H1 = (const uint32_t*)H;
    float sw = g_selfw[warp];
    uint32_t hv = H1[(size_t)warp * 32 + lane];
    float2 f0 = __half22float2(*(__half2*)&hv);
    float2 acc = make_float2(sw * f0.x, sw * f0.y);
    int beg = g_rowptr[warp], end = g_rowptr[warp + 1];
    for (int j = beg; j < end; j += 8) {
        int4 e0 = *(const int4*)&g_edge[j];
        int4 e1 = *(const int4*)&g_edge[j + 2];
        int4 e2 = *(const int4*)&g_edge[j + 4];
        int4 e3 = *(const int4*)&g_edge[j + 6];
        uint32_t g0 = H1[(size_t)e0.x * 32 + lane];
        uint32_t g1 = H1[(size_t)e0.z * 32 + lane];
        uint32_t g2 = H1[(size_t)e1.x * 32 + lane];
        uint32_t g3 = H1[(size_t)e1.z * 32 + lane];
        uint32_t g4 = H1[(size_t)e2.x * 32 + lane];
        uint32_t g5 = H1[(size_t)e2.z * 32 + lane];
        uint32_t g6 = H1[(size_t)e3.x * 32 + lane];
        uint32_t g7 = H1[(size_t)e3.z * 32 + lane];
        float2 a0 = __half22float2(*(__half2*)&g0);
        float2 a1 = __half22float2(*(__half2*)&g1);
        float2 a2 = __half22float2(*(__half2*)&g2);
        float2 a3 = __half22float2(*(__half2*)&g3);
        float2 a4 = __half22float2(*(__half2*)&g4);
        float2 a5 = __half22float2(*(__half2*)&g5);
        float2 a6 = __half22float2(*(__half2*)&g6);
        float2 a7 = __half22float2(*(__half2*)&g7);
        acc.x += __int_as_float(e0.y) * a0.x; acc.y += __int_as_float(e0.y) * a0.y;
        acc.x += __int_as_float(e0.w) * a1.x; acc.y += __int_as_float(e0.w) * a1.y;
        acc.x += __int_as_float(e1.y) * a2.x; acc.y += __int_as_float(e1.y) * a2.y;
        acc.x += __int_as_float(e1.w) * a3.x; acc.y += __int_as_float(e1.w) * a3.y;
        acc.x += __int_as_float(e2.y) * a4.x; acc.y += __int_as_float(e2.y) * a4.y;
        acc.x += __int_as_float(e2.w) * a5.x; acc.y += __int_as_float(e2.w) * a5.y;
        acc.x += __int_as_float(e3.y) * a6.x; acc.y += __int_as_float(e3.y) * a6.y;
        acc.x += __int_as_float(e3.w) * a7.x; acc.y += __int_as_float(e3.w) * a7.y;
    }
    float2 b2 = ((const float2*)bias)[lane];
    acc.x += b2.x; acc.y += b2.y;
    ((float2*)out)[(size_t)warp * 32 + lane] = acc;
}

// ---------------- global mean pool ----------------
__global__ void k_pool(const float* __restrict__ Hout, float* __restrict__ out) {
    int g = blockIdx.x;
    int t = threadIdx.x;
    int f = t & 63, grp = t >> 6;
    __shared__ float sh[256];
    int s = g_gstart[g], e = g_gend[g];
    float acc = 0.f;
    if (s < e) {
        for (int i = s + grp; i < e; i += 4) acc += Hout[(size_t)i * 64 + f];
    }
    sh[t] = acc;
    __syncthreads();
    if (grp == 0) {
        float v = sh[f] + sh[64 + f] + sh[128 + f] + sh[192 + f];
        int cnt = (s < e) ? (e - s) : 0;
        float denom = (cnt > 0) ? (float)cnt : 1.f;
        out[g * 64 + f] = v / denom;
    }
}

// ---------------- launch ----------------
extern "C" void kernel_launch(void* const* d_in, const int* in_sizes, int n_in,
                              void* d_out, int out_size) {
    const float* x  = (const float*)d_in[0];
    const void*  ei = d_in[1];
    const void*  batch = d_in[2];
    const float* W1 = (const float*)d_in[3];
    const float* b1 = (const float*)d_in[4];
    const float* W2 = (const float*)d_in[5];
    const float* b2 = (const float*)d_in[6];
    const float* W3 = (const float*)d_in[7];
    const float* b3 = (const float*)d_in[8];
    float* out = (float*)d_out;

    int n = in_sizes[0] / FDIM;
    int e = in_sizes[1] / 2;
    if (n > NMAX) n = NMAX;
    if (e > EMAX) e = EMAX;

    int ge  = (e + 255) / 256;
    int nch = (n + 1023) / 1024;

    void* p;
    cudaGetSymbolAddress(&p, g_Th);  __half* pTh = (__half*)p;
    cudaGetSymbolAddress(&p, g_Gh);  __nv_bfloat16* pGh = (__nv_bfloat16*)p;
    cudaGetSymbolAddress(&p, g_G);   float* pG = (float*)p;
    cudaGetSymbolAddress(&p, g_cntflags); int* pCnt = (int*)p;

    const int SMEM_G1  = 3 * 128 * 136 * 2;                          // 104448
    const int SMEM128  = 2 * 128 * (128 + 8) * 2 + 4 * 128 * 40 * 2; // 110592
    const int SMEM64   = 2 * 128 * (64 + 8) * 2 + 4 * 128 * 40 * 2;  // 77824
    cudaFuncSetAttribute(k_layer1,       cudaFuncAttributeMaxDynamicSharedMemorySize, SMEM_G1);
    cudaFuncSetAttribute(k_gemm_bf<128>, cudaFuncAttributeMaxDynamicSharedMemorySize, SMEM128);
    cudaFuncSetAttribute(k_gemm_bf<64>,  cudaFuncAttributeMaxDynamicSharedMemorySize, SMEM64);

    int ggemm = (n + 127) / 128;
    int gagg  = (n * 32 + 255) / 256;

    cudaMemsetAsync(pCnt, 0, (NMAX + 128) * sizeof(int));
    k_layer1<<<ggemm, 256, SMEM_G1>>>(x, W1, ei, batch, pTh, n, e);     // K1
    k_prefix<<<nch, 256>>>(n);                                          // K2
    k_csr<<<ge, 256>>>(e);                                              // K3
    k_agg128<<<gagg, 256>>>(pTh, b1, pGh, n);                           // K4 <- ncu slot
    k_gemm_bf<128><<<ggemm, 256, SMEM128>>>(pGh, W2, pTh, n);           // K5
    k_agg128<<<gagg, 256>>>(pTh, b2, pGh, n);                           // K6
    k_gemm_bf<64><<<ggemm, 256, SMEM64>>>(pGh, W3, pTh, n);             // K7
    k_agg64<<<gagg, 256>>>(pTh, b3, pG, n);                             // K8
    k_pool<<<NGR, 256>>>(pG, out);                                      // K9
}

// round 17
// speedup vs baseline: 1.0232x; 1.0232x over previous
#include <cuda_runtime.h>
#include <cuda_fp16.h>
#include <cuda_bf16.h>
#include <cstdint>
#include <limits.h>

#define NMAX 100000
#define NPAD 100096   // 782 * 128: gemm2/3 A-tile cp.async never reads past g_Gh
#define EMAX 1600000
#define EPAD (EMAX + 8 * NMAX)   // padded CSR capacity
#define NGR  64
#define FDIM 128
#define FLAGBIT 0x80000000u

// ---------------- device scratch ----------------
static __device__ __half         g_Th[(size_t)NPAD * FDIM];
static __device__ __nv_bfloat16  g_Gh[(size_t)NPAD * FDIM];
static __device__ float          g_G[(size_t)NMAX * 64];
static __device__ int    g_cntflags[NMAX + 128];   // [0..n)=cnt, [NMAX..]=scan flags (memset 0)
static __device__ int    g_rowptr[NMAX + 1];       // padded offsets (multiples of 8)
static __device__ int    g_cursor[NMAX];
static __device__ int2   g_edge[EPAD];             // {src, half2(w,w) bits}; pad slots = {0,0}
static __device__ float  g_dinv[NMAX];
static __device__ float  g_selfw[NMAX];
static __device__ int    g_gstart[NGR];
static __device__ int    g_gend[NGR];
static __device__ int    g_src32[EMAX];
static __device__ int    g_dst32[EMAX];

// ---------------- helpers ----------------
__device__ __forceinline__ void mma_bf16(float* c, const uint32_t* a, const uint32_t* b) {
    asm volatile("mma.sync.aligned.m16n8k16.row.col.f32.bf16.bf16.f32 "
        "{%0,%1,%2,%3}, {%4,%5,%6,%7}, {%8,%9}, {%0,%1,%2,%3};"
        : "+f"(c[0]), "+f"(c[1]), "+f"(c[2]), "+f"(c[3])
        : "r"(a[0]), "r"(a[1]), "r"(a[2]), "r"(a[3]), "r"(b[0]), "r"(b[1]));
}
__device__ __forceinline__ void ldsm_x4(uint32_t* r, uint32_t addr) {
    asm volatile("ldmatrix.sync.aligned.m8n8.x4.shared.b16 {%0,%1,%2,%3}, [%4];"
        : "=r"(r[0]), "=r"(r[1]), "=r"(r[2]), "=r"(r[3]) : "r"(addr));
}
__device__ __forceinline__ void ldsm_x2t(uint32_t* r, uint32_t addr) {
    asm volatile("ldmatrix.sync.aligned.m8n8.x2.trans.shared.b16 {%0,%1}, [%2];"
        : "=r"(r[0]), "=r"(r[1]) : "r"(addr));
}
__device__ __forceinline__ void cp_async16(uint32_t dst, const void* src) {
    asm volatile("cp.async.ca.shared.global [%0], [%1], 16;" :: "r"(dst), "l"(src));
}
__device__ __forceinline__ void split_store(__nv_bfloat16* ph, __nv_bfloat16* pl, float4 v) {
    __nv_bfloat162 h0 = __float22bfloat162_rn(make_float2(v.x, v.y));
    __nv_bfloat162 h1 = __float22bfloat162_rn(make_float2(v.z, v.w));
    float2 r0 = make_float2(v.x - __low2float(h0), v.y - __high2float(h0));
    float2 r1 = make_float2(v.z - __low2float(h1), v.w - __high2float(h1));
    *(__nv_bfloat162*)ph       = h0;
    *(__nv_bfloat162*)(ph + 2) = h1;
    *(__nv_bfloat162*)pl       = __float22bfloat162_rn(r0);
    *(__nv_bfloat162*)(pl + 2) = __float22bfloat162_rn(r1);
}

// ---------------- K1: fused gemm1 + preprocessing ----------------
__global__ __launch_bounds__(256) void k_layer1(
    const float* __restrict__ A, const float* __restrict__ W,
    const void* __restrict__ ei, const void* __restrict__ batch,
    __half* __restrict__ C, int M, int e) {
    constexpr int BN = 128, NJ = 8, WS = 136;
    extern __shared__ __nv_bfloat16 smem[];
    __nv_bfloat16* sWh = smem;
    __nv_bfloat16* sWl = smem + 128 * WS;
    __nv_bfloat16* sA  = smem + 2 * 128 * WS;
    __shared__ int s_is64;

    int tid = threadIdx.x;
    if (tid == 0) {
        const long long* p = (const long long*)ei;
        int ok = 1;
        int m = e < 8 ? e : 8;
        for (int k = 0; k < m; k++) {
            long long v = p[k];
            if (v < 0 || v >= (long long)M) ok = 0;
        }
        s_is64 = ok;
    }
    __syncthreads();
    int is64 = s_is64;
    int m0 = blockIdx.x * 128;

#pragma unroll
    for (int it = 0; it < 16; it++) {
        int idx = tid + it * 256;
        int r = idx >> 5, q = idx & 31;
        float4 v = ((const float4*)W)[idx];
        split_store(&sWh[r * WS + q * 4], &sWl[r * WS + q * 4], v);
    }
#pragma unroll
    for (int it = 0; it < 16; it++) {
        int idx = tid + it * 256;
        int r = idx >> 5, q = idx & 31;
        int row = m0 + r;
        float4 v = make_float4(0.f, 0.f, 0.f, 0.f);
        if (row < M) v = ((const float4*)A)[(size_t)row * 32 + q];
        __nv_bfloat162 h0 = __float22bfloat162_rn(make_float2(v.x, v.y));
        __nv_bfloat162 h1 = __float22bfloat162_rn(make_float2(v.z, v.w));
        *(__nv_bfloat162*)&sA[r * WS + q * 4]     = h0;
        *(__nv_bfloat162*)&sA[r * WS + q * 4 + 2] = h1;
    }

    int nt = gridDim.x * 256;
    for (int i = blockIdx.x * 256 + tid; i < e; i += nt) {
        int s, d;
        if (is64) {
            const long long* p = (const long long*)ei;
            s = (int)p[i]; d = (int)p[(size_t)e + i];
        } else {
            const int* p = (const int*)ei;
            s = p[i]; d = p[(size_t)e + i];
        }
        g_src32[i] = s;
        g_dst32[i] = d;
        atomicAdd(&g_cntflags[d], 1);
    }
    for (int i = blockIdx.x * 256 + tid; i < M; i += nt) {
        int b, bp;
        if (is64) {
            const long long* p = (const long long*)batch;
            b = (int)p[i];
            bp = (i > 0) ? (int)p[i - 1] : -1;
        } else {
            const int* p = (const int*)batch;
            b = p[i];
            bp = (i > 0) ? p[i - 1] : -1;
        }
        if (i == 0) {
            g_gstart[b] = 0;
            for (int q = 0; q < b; q++) { g_gstart[q] = 0; g_gend[q] = 0; }
        } else if (bp != b) {
            g_gend[bp] = i;
            g_gstart[b] = i;
            for (int q = bp + 1; q < b; q++) { g_gstart[q] = i; g_gend[q] = i; }
        }
        if (i == M - 1) {
            g_gend[b] = M;
            for (int q = b + 1; q < NGR; q++) { g_gstart[q] = M; g_gend[q] = M; }
        }
    }
    __syncthreads();

    int w = tid >> 5, lane = tid & 31;
    int grp = lane >> 2, tig = lane & 3;
    int wm = (w & 3) * 32;
    int wn = (w >> 2) * (NJ * 8);
    int l15 = lane & 15;

    float c[2][NJ][4];
#pragma unroll
    for (int i = 0; i < 2; i++)
#pragma unroll
        for (int j = 0; j < NJ; j++)
#pragma unroll
            for (int q = 0; q < 4; q++) c[i][j][q] = 0.f;

#pragma unroll
    for (int k16 = 0; k16 < 128; k16 += 16) {
        uint32_t a[2][4];
#pragma unroll
        for (int i = 0; i < 2; i++) {
            uint32_t addr = (uint32_t)__cvta_generic_to_shared(
                &sA[(wm + i * 16 + l15) * WS + k16 + (lane >> 4) * 8]);
            ldsm_x4(a[i], addr);
        }
        uint32_t b[NJ][2];
#pragma unroll
        for (int j = 0; j < NJ; j++) {
            uint32_t addr = (uint32_t)__cvta_generic_to_shared(
                &sWh[(k16 + l15) * WS + wn + j * 8]);
            ldsm_x2t(b[j], addr);
        }
#pragma unroll
        for (int i = 0; i < 2; i++)
#pragma unroll
            for (int j = 0; j < NJ; j++) mma_bf16(c[i][j], a[i], b[j]);
#pragma unroll
        for (int j = 0; j < NJ; j++) {
            uint32_t addr = (uint32_t)__cvta_generic_to_shared(
                &sWl[(k16 + l15) * WS + wn + j * 8]);
            ldsm_x2t(b[j], addr);
        }
#pragma unroll
        for (int i = 0; i < 2; i++)
#pragma unroll
            for (int j = 0; j < NJ; j++) mma_bf16(c[i][j], a[i], b[j]);
    }

#pragma unroll
    for (int i = 0; i < 2; i++) {
        int r0 = m0 + wm + i * 16 + grp;
        int r1 = r0 + 8;
#pragma unroll
        for (int j = 0; j < NJ; j++) {
            int col = wn + j * 8 + tig * 2;
            if (r0 < M) *(__half2*)&C[(size_t)r0 * BN + col] = __floats2half2_rn(c[i][j][0], c[i][j][1]);
            if (r1 < M) *(__half2*)&C[(size_t)r1 * BN + col] = __floats2half2_rn(c[i][j][2], c[i][j][3]);
        }
    }
}

// ---------------- K2: lookback scan over padded counts (+ dinv/selfw/cursor + pad writes) ----
__global__ void k_prefix(int n) {
    __shared__ int sh[256];
    __shared__ int s_base;
    int b = blockIdx.x, t = threadIdx.x;
    int idx0 = b * 1024 + t * 4;
    int c[4]; int tot = 0;
#pragma unroll
    for (int j = 0; j < 4; j++) {
        int id = idx0 + j;
        c[j] = (id < n) ? g_cntflags[id] : 0;
        tot += (c[j] + 7) & ~7;
    }
    sh[t] = tot;
    __syncthreads();
    for (int d = 1; d < 256; d <<= 1) {
        int v = (t >= d) ? sh[t - d] : 0;
        __syncthreads();
        sh[t] += v;
        __syncthreads();
    }
    int incl = sh[t];
    int agg  = sh[255];
    if (t == 0) atomicExch(&g_cntflags[NMAX + b], (int)((unsigned)agg | FLAGBIT));
    int partial = 0;
    for (int j = t; j < b; j += 256) {
        int v;
        do { v = *(volatile int*)&g_cntflags[NMAX + j]; } while (!((unsigned)v & FLAGBIT));
        partial += (int)((unsigned)v & ~FLAGBIT);
    }
    __syncthreads();
    sh[t] = partial;
    __syncthreads();
    for (int d = 128; d > 0; d >>= 1) {
        if (t < d) sh[t] += sh[t + d];
        __syncthreads();
    }
    if (t == 0) s_base = sh[0];
    __syncthreads();
    int run = s_base + incl - tot;
#pragma unroll
    for (int j = 0; j < 4; j++) {
        int id = idx0 + j;
        if (id < n) {
            int pc = (c[j] + 7) & ~7;
            g_rowptr[id] = run;
            g_cursor[id] = run;
            float di = rsqrtf((float)(c[j] + 1));
            g_dinv[id] = di;
            g_selfw[id] = di * di;
            for (int q = c[j]; q < pc; q++) g_edge[run + q] = make_int2(0, 0);
            run += pc;
            if (id == n - 1) g_rowptr[n] = run;
        }
    }
}

// ---------------- K3: CSR build (weight packed as half2) ----------------
__global__ void k_csr(int e) {
    int i = blockIdx.x * blockDim.x + threadIdx.x;
    if (i >= e) return;
    int s = g_src32[i], d = g_dst32[i];
    float w = g_dinv[s] * g_dinv[d];
    __half2 wh = __float2half2_rn(w);
    int pos = atomicAdd(&g_cursor[d], 1);
    g_edge[pos] = make_int2(s, *(int*)&wh);
}

// ---------------- gemm2/3 ----------------
template <int BN>
__global__ __launch_bounds__(256) void k_gemm_bf(const __nv_bfloat16* __restrict__ A,
                                                 const float* __restrict__ W,
                                                 __half* __restrict__ C, int M) {
    constexpr int NJ = BN / 16;
    constexpr int WS = BN + 8;
    extern __shared__ __nv_bfloat16 smem[];
    __nv_bfloat16* sWh = smem;
    __nv_bfloat16* sWl = smem + 128 * WS;
    __nv_bfloat16* sA  = smem + 2 * 128 * WS;

    int tid = threadIdx.x;
    int w = tid >> 5, lane = tid & 31;
    int grp = lane >> 2, tig = lane & 3;
    int wm = (w & 3) * 32;
    int wn = (w >> 2) * (NJ * 8);
    int m0 = blockIdx.x * 128;
    int l15 = lane & 15;

#pragma unroll
    for (int t = 0; t < 4; t++) {
#pragma unroll
        for (int cch = 0; cch < 2; cch++) {
            int idx = tid + cch * 256;
            int row = idx >> 2, q = idx & 3;
            cp_async16((uint32_t)__cvta_generic_to_shared(&sA[(t * 128 + row) * 40 + q * 8]),
                       &A[(size_t)(m0 + row) * 128 + t * 32 + q * 8]);
        }
        asm volatile("cp.async.commit_group;");
    }
#pragma unroll
    for (int it = tid; it < 128 * BN / 4; it += 256) {
        int r = it / (BN / 4), q = it % (BN / 4);
        float4 v = ((const float4*)W)[it];
        split_store(&sWh[r * WS + q * 4], &sWl[r * WS + q * 4], v);
    }

    float c[2][NJ][4];
#pragma unroll
    for (int i = 0; i < 2; i++)
#pragma unroll
        for (int j = 0; j < NJ; j++)
#pragma unroll
            for (int q = 0; q < 4; q++) c[i][j][q] = 0.f;

#pragma unroll
    for (int t = 0; t < 4; t++) {
        if (t == 0)      asm volatile("cp.async.wait_group 3;");
        else if (t == 1) asm volatile("cp.async.wait_group 2;");
        else if (t == 2) asm volatile("cp.async.wait_group 1;");
        else             asm volatile("cp.async.wait_group 0;");
        __syncthreads();
#pragma unroll
        for (int k16 = 0; k16 < 32; k16 += 16) {
            int krow = t * 32 + k16;
            uint32_t a[2][4];
#pragma unroll
            for (int i = 0; i < 2; i++) {
                uint32_t addr = (uint32_t)__cvta_generic_to_shared(
                    &sA[(t * 128 + wm + i * 16 + l15) * 40 + k16 + (lane >> 4) * 8]);
                ldsm_x4(a[i], addr);
            }
            uint32_t b[NJ][2];
#pragma unroll
            for (int j = 0; j < NJ; j++) {
                uint32_t addr = (uint32_t)__cvta_generic_to_shared(
                    &sWh[(krow + l15) * WS + wn + j * 8]);
                ldsm_x2t(b[j], addr);
            }
#pragma unroll
            for (int i = 0; i < 2; i++)
#pragma unroll
                for (int j = 0; j < NJ; j++) mma_bf16(c[i][j], a[i], b[j]);
#pragma unroll
            for (int j = 0; j < NJ; j++) {
                uint32_t addr = (uint32_t)__cvta_generic_to_shared(
                    &sWl[(krow + l15) * WS + wn + j * 8]);
                ldsm_x2t(b[j], addr);
            }
#pragma unroll
            for (int i = 0; i < 2; i++)
#pragma unroll
                for (int j = 0; j < NJ; j++) mma_bf16(c[i][j], a[i], b[j]);
        }
    }

#pragma unroll
    for (int i = 0; i < 2; i++) {
        int r0 = m0 + wm + i * 16 + grp;
        int r1 = r0 + 8;
#pragma unroll
        for (int j = 0; j < NJ; j++) {
            int col = wn + j * 8 + tig * 2;
            if (r0 < M) *(__half2*)&C[(size_t)r0 * BN + col] = __floats2half2_rn(c[i][j][0], c[i][j][1]);
            if (r1 < M) *(__half2*)&C[(size_t)r1 * BN + col] = __floats2half2_rn(c[i][j][2], c[i][j][3]);
        }
    }
}

// ---------------- aggregation: padded CSR, uniform int4 loads, HFMA2 accumulation ----------------
__global__ __launch_bounds__(256) void k_agg128(const __half* __restrict__ H,
                                                const float* __restrict__ bias,
                                                __nv_bfloat16* __restrict__ out, int n) {
    int warp = (blockIdx.x * blockDim.x + threadIdx.x) >> 5;
    if (warp >= n) return;
    int lane = threadIdx.x & 31;
    const uint2* H2 = (const uint2*)H;
    __half2 swh = __float2half2_rn(g_selfw[warp]);
    uint2 hv = H2[(size_t)warp * 32 + lane];
    __half2 acc0 = __hmul2(swh, *(__half2*)&hv.x);
    __half2 acc1 = __hmul2(swh, *(__half2*)&hv.y);
    int beg = g_rowptr[warp], end = g_rowptr[warp + 1];
    for (int j = beg; j < end; j += 8) {
        int4 e0 = *(const int4*)&g_edge[j];
        int4 e1 = *(const int4*)&g_edge[j + 2];
        int4 e2 = *(const int4*)&g_edge[j + 4];
        int4 e3 = *(const int4*)&g_edge[j + 6];
        uint2 g0 = H2[(size_t)e0.x * 32 + lane];
        uint2 g1 = H2[(size_t)e0.z * 32 + lane];
        uint2 g2 = H2[(size_t)e1.x * 32 + lane];
        uint2 g3 = H2[(size_t)e1.z * 32 + lane];
        uint2 g4 = H2[(size_t)e2.x * 32 + lane];
        uint2 g5 = H2[(size_t)e2.z * 32 + lane];
        uint2 g6 = H2[(size_t)e3.x * 32 + lane];
        uint2 g7 = H2[(size_t)e3.z * 32 + lane];
        acc0 = __hfma2(*(__half2*)&e0.y, *(__half2*)&g0.x, acc0);
        acc1 = __hfma2(*(__half2*)&e0.y, *(__half2*)&g0.y, acc1);
        acc0 = __hfma2(*(__half2*)&e0.w, *(__half2*)&g1.x, acc0);
        acc1 = __hfma2(*(__half2*)&e0.w, *(__half2*)&g1.y, acc1);
        acc0 = __hfma2(*(__half2*)&e1.y, *(__half2*)&g2.x, acc0);
        acc1 = __hfma2(*(__half2*)&e1.y, *(__half2*)&g2.y, acc1);
        acc0 = __hfma2(*(__half2*)&e1.w, *(__half2*)&g3.x, acc0);
        acc1 = __hfma2(*(__half2*)&e1.w, *(__half2*)&g3.y, acc1);
        acc0 = __hfma2(*(__half2*)&e2.y, *(__half2*)&g4.x, acc0);
        acc1 = __hfma2(*(__half2*)&e2.y, *(__half2*)&g4.y, acc1);
        acc0 = __hfma2(*(__half2*)&e2.w, *(__half2*)&g5.x, acc0);
        acc1 = __hfma2(*(__half2*)&e2.w, *(__half2*)&g5.y, acc1);
        acc0 = __hfma2(*(__half2*)&e3.y, *(__half2*)&g6.x, acc0);
        acc1 = __hfma2(*(__half2*)&e3.y, *(__half2*)&g6.y, acc1);
        acc0 = __hfma2(*(__half2*)&e3.w, *(__half2*)&g7.x, acc0);
        acc1 = __hfma2(*(__half2*)&e3.w, *(__half2*)&g7.y, acc1);
    }
    float2 f0 = __half22float2(acc0);
    float2 f1 = __half22float2(acc1);
    float4 b4 = ((const float4*)bias)[lane];
    float ox = fmaxf(f0.x + b4.x, 0.f);
    float oy = fmaxf(f0.y + b4.y, 0.f);
    float oz = fmaxf(f1.x + b4.z, 0.f);
    float ow = fmaxf(f1.y + b4.w, 0.f);
    __nv_bfloat162 o0 = __float22bfloat162_rn(make_float2(ox, oy));
    __nv_bfloat162 o1 = __float22bfloat162_rn(make_float2(oz, ow));
    uint2 o; o.x = *(uint32_t*)&o0; o.y = *(uint32_t*)&o1;
    ((uint2*)out)[(size_t)warp * 32 + lane] = o;
}

__global__ __launch_bounds__(256) void k_agg64(const __half* __restrict__ H,
                                               const float* __restrict__ bias,
                                               float* __restrict__ out, int n) {
    int warp = (blockIdx.x * blockDim.x + threadIdx.x) >> 5;
    if (warp >= n) return;
    int lane = threadIdx.x & 31;
    const uint32_t* H1 = (const uint32_t*)H;
    __half2 swh = __float2half2_rn(g_selfw[warp]);
    uint32_t hv = H1[(size_t)warp * 32 + lane];
    __half2 acc = __hmul2(swh, *(__half2*)&hv);
    int beg = g_rowptr[warp], end = g_rowptr[warp + 1];
    for (int j = beg; j < end; j += 8) {
        int4 e0 = *(const int4*)&g_edge[j];
        int4 e1 = *(const int4*)&g_edge[j + 2];
        int4 e2 = *(const int4*)&g_edge[j + 4];
        int4 e3 = *(const int4*)&g_edge[j + 6];
        uint32_t g0 = H1[(size_t)e0.x * 32 + lane];
        uint32_t g1 = H1[(size_t)e0.z * 32 + lane];
        uint32_t g2 = H1[(size_t)e1.x * 32 + lane];
        uint32_t g3 = H1[(size_t)e1.z * 32 + lane];
        uint32_t g4 = H1[(size_t)e2.x * 32 + lane];
        uint32_t g5 = H1[(size_t)e2.z * 32 + lane];
        uint32_t g6 = H1[(size_t)e3.x * 32 + lane];
        uint32_t g7 = H1[(size_t)e3.z * 32 + lane];
        acc = __hfma2(*(__half2*)&e0.y, *(__half2*)&g0, acc);
        acc = __hfma2(*(__half2*)&e0.w, *(__half2*)&g1, acc);
        acc = __hfma2(*(__half2*)&e1.y, *(__half2*)&g2, acc);
        acc = __hfma2(*(__half2*)&e1.w, *(__half2*)&g3, acc);
        acc = __hfma2(*(__half2*)&e2.y, *(__half2*)&g4, acc);
        acc = __hfma2(*(__half2*)&e2.w, *(__half2*)&g5, acc);
        acc = __hfma2(*(__half2*)&e3.y, *(__half2*)&g6, acc);
        acc = __hfma2(*(__half2*)&e3.w, *(__half2*)&g7, acc);
    }
    float2 f0 = __half22float2(acc);
    float2 b2 = ((const float2*)bias)[lane];
    f0.x += b2.x; f0.y += b2.y;
    ((float2*)out)[(size_t)warp * 32 + lane] = f0;
}

// ---------------- global mean pool ----------------
__global__ void k_pool(const float* __restrict__ Hout, float* __restrict__ out) {
    int g = blockIdx.x;
    int t = threadIdx.x;
    int f = t & 63, grp = t >> 6;
    __shared__ float sh[256];
    int s = g_gstart[g], e = g_gend[g];
    float acc = 0.f;
    if (s < e) {
        for (int i = s + grp; i < e; i += 4) acc += Hout[(size_t)i * 64 + f];
    }
    sh[t] = acc;
    __syncthreads();
    if (grp == 0) {
        float v = sh[f] + sh[64 + f] + sh[128 + f] + sh[192 + f];
        int cnt = (s < e) ? (e - s) : 0;
        float denom = (cnt > 0) ? (float)cnt : 1.f;
        out[g * 64 + f] = v / denom;
    }
}

// ---------------- launch ----------------
extern "C" void kernel_launch(void* const* d_in, const int* in_sizes, int n_in,
                              void* d_out, int out_size) {
    const float* x  = (const float*)d_in[0];
    const void*  ei = d_in[1];
    const void*  batch = d_in[2];
    const float* W1 = (const float*)d_in[3];
    const float* b1 = (const float*)d_in[4];
    const float* W2 = (const float*)d_in[5];
    const float* b2 = (const float*)d_in[6];
    const float* W3 = (const float*)d_in[7];
    const float* b3 = (const float*)d_in[8];
    float* out = (float*)d_out;

    int n = in_sizes[0] / FDIM;
    int e = in_sizes[1] / 2;
    if (n > NMAX) n = NMAX;
    if (e > EMAX) e = EMAX;

    int ge  = (e + 255) / 256;
    int nch = (n + 1023) / 1024;

    void* p;
    cudaGetSymbolAddress(&p, g_Th);  __half* pTh = (__half*)p;
    cudaGetSymbolAddress(&p, g_Gh);  __nv_bfloat16* pGh = (__nv_bfloat16*)p;
    cudaGetSymbolAddress(&p, g_G);   float* pG = (float*)p;
    cudaGetSymbolAddress(&p, g_cntflags); int* pCnt = (int*)p;

    const int SMEM_G1  = 3 * 128 * 136 * 2;                          // 104448
    const int SMEM128  = 2 * 128 * (128 + 8) * 2 + 4 * 128 * 40 * 2; // 110592
    const int SMEM64   = 2 * 128 * (64 + 8) * 2 + 4 * 128 * 40 * 2;  // 77824
    cudaFuncSetAttribute(k_layer1,       cudaFuncAttributeMaxDynamicSharedMemorySize, SMEM_G1);
    cudaFuncSetAttribute(k_gemm_bf<128>, cudaFuncAttributeMaxDynamicSharedMemorySize, SMEM128);
    cudaFuncSetAttribute(k_gemm_bf<64>,  cudaFuncAttributeMaxDynamicSharedMemorySize, SMEM64);

    int ggemm = (n + 127) / 128;
    int gagg  = (n * 32 + 255) / 256;

    cudaMemsetAsync(pCnt, 0, (NMAX + 128) * sizeof(int));
    k_layer1<<<ggemm, 256, SMEM_G1>>>(x, W1, ei, batch, pTh, n, e);     // K1
    k_prefix<<<nch, 256>>>(n);                                          // K2
    k_csr<<<ge, 256>>>(e);                                              // K3
    k_agg128<<<gagg, 256>>>(pTh, b1, pGh, n);                           // K4 <- ncu slot
    k_gemm_bf<128><<<ggemm, 256, SMEM128>>>(pGh, W2, pTh, n);           // K5
    k_agg128<<<gagg, 256>>>(pTh, b2, pGh, n);                           // K6
    k_gemm_bf<64><<<ggemm, 256, SMEM64>>>(pGh, W3, pTh, n);             // K7
    k_agg64<<<gagg, 256>>>(pTh, b3, pG, n);                             // K8
    k_pool<<<NGR, 256>>>(pG, out);                                      // K9
}